// round 1
// baseline (speedup 1.0000x reference)
#include <cuda_runtime.h>

#define BATCH   8192
#define DIN     4096
#define DHID    4096
#define NM      8
#define NH      512
#define AG      512
#define NOUT    10

typedef unsigned long long ull;

// 134 MB scratch for the hidden activation (static __device__ — allowed).
__device__ float g_h[(size_t)BATCH * DHID];

__device__ __forceinline__ ull packdup(float v) {
    ull r;
    asm("mov.b64 %0, {%1, %1};" : "=l"(r) : "r"(__float_as_uint(v)));
    return r;
}
__device__ __forceinline__ void fma2(ull& d, ull a, ull b) {
    // packed f32x2 FMA — doubles fp32 FMA throughput vs FFMA (rt_SMSP=2 either way)
    asm("fma.rn.f32x2 %0, %1, %2, %0;" : "+l"(d) : "l"(a), "l"(b));
}

// ---------------------------------------------------------------------------
// Kernel 1: h = relu(X_m @ W1_m^T + b1_m) for each of 8 diagonal blocks.
// Block tile 128x128, BK=16, 256 threads, 8x8 micro-tile as 8x(4 f32x2 pairs).
// Both A (x) and B (W1 rows) are K-contiguous -> coalesced float4 loads.
// ---------------------------------------------------------------------------
__global__ __launch_bounds__(256, 2)
void mod_gemm1(const float* __restrict__ x, const float* __restrict__ W1,
               const float* __restrict__ b1) {
    __shared__ float As[16][132];   // [k][row], padded (528B rows keep 16B align)
    __shared__ float Bs[16][132];   // [k][col]

    const int m = blockIdx.z;
    const int rowBase = blockIdx.y * 128;
    const int colBase = blockIdx.x * 128;       // within this module's 512 outputs
    const int tid = threadIdx.x;
    const int tx = tid & 15;
    const int ty = tid >> 4;

    const float* Ag = x  + (size_t)rowBase * DIN + m * AG;
    const float* Bg = W1 + (size_t)(m * NH + colBase) * DIN + m * AG;

    ull acc[8][4];
    #pragma unroll
    for (int i = 0; i < 8; i++)
        #pragma unroll
        for (int j = 0; j < 4; j++) acc[i][j] = 0ULL;

    for (int k0 = 0; k0 < AG; k0 += 16) {
        // Stage tiles: 512 float4 per operand, 2 per thread.
        #pragma unroll
        for (int s = 0; s < 2; s++) {
            int p  = tid + s * 256;
            int r  = p >> 2;
            int kv = (p & 3) * 4;
            float4 av = *(const float4*)(Ag + (size_t)r * DIN + k0 + kv);
            As[kv + 0][r] = av.x; As[kv + 1][r] = av.y;
            As[kv + 2][r] = av.z; As[kv + 3][r] = av.w;
            float4 bv = *(const float4*)(Bg + (size_t)r * DIN + k0 + kv);
            Bs[kv + 0][r] = bv.x; Bs[kv + 1][r] = bv.y;
            Bs[kv + 2][r] = bv.z; Bs[kv + 3][r] = bv.w;
        }
        __syncthreads();
        #pragma unroll
        for (int k = 0; k < 16; k++) {
            float4 a0 = *(const float4*)&As[k][ty * 8];
            float4 a1 = *(const float4*)&As[k][ty * 8 + 4];
            ulonglong2 q0 = *(const ulonglong2*)&Bs[k][tx * 8];
            ulonglong2 q1 = *(const ulonglong2*)&Bs[k][tx * 8 + 4];
            ull bq[4] = {q0.x, q0.y, q1.x, q1.y};
            ull ap[8] = {packdup(a0.x), packdup(a0.y), packdup(a0.z), packdup(a0.w),
                         packdup(a1.x), packdup(a1.y), packdup(a1.z), packdup(a1.w)};
            #pragma unroll
            for (int i = 0; i < 8; i++)
                #pragma unroll
                for (int j = 0; j < 4; j++)
                    fma2(acc[i][j], ap[i], bq[j]);
        }
        __syncthreads();
    }

    // Epilogue: +bias, relu, store to g_h. Bias depends only on column -> hoist.
    const int cb = colBase + tx * 8;
    float2 bias[4];
    #pragma unroll
    for (int j = 0; j < 4; j++) {
        bias[j].x = b1[m * NH + cb + 2 * j];
        bias[j].y = b1[m * NH + cb + 2 * j + 1];
    }
    #pragma unroll
    for (int i = 0; i < 8; i++) {
        int gr = rowBase + ty * 8 + i;
        float* hp = g_h + (size_t)gr * DHID + m * NH + cb;
        #pragma unroll
        for (int j = 0; j < 4; j++) {
            float lo = __uint_as_float((unsigned)(acc[i][j] & 0xffffffffULL));
            float hi = __uint_as_float((unsigned)(acc[i][j] >> 32));
            float2 r;
            r.x = fmaxf(lo + bias[j].x, 0.f);
            r.y = fmaxf(hi + bias[j].y, 0.f);
            *(float2*)(hp + 2 * j) = r;
        }
    }
}

// ---------------------------------------------------------------------------
// Kernel 2: y = h_m @ W2_m^T + b2_m  (N=10 per module). One thread per row,
// W2 block transposed into smem as [k][o] so per-k weight reads are pure
// broadcasts (conflict-free).
// ---------------------------------------------------------------------------
__global__ __launch_bounds__(256)
void mod_gemm2(const float* __restrict__ W2, const float* __restrict__ b2,
               float* __restrict__ y) {
    __shared__ float Ws[NH][12];    // [k][o], 48B rows keep float4 alignment
    const int m   = blockIdx.y;
    const int tid = threadIdx.x;

    for (int idx = tid; idx < NOUT * NH; idx += 256) {
        int o = idx >> 9;
        int k = idx & (NH - 1);
        Ws[k][o] = W2[(size_t)(m * NOUT + o) * DHID + m * NH + k];
    }
    __syncthreads();

    const int row = blockIdx.x * 256 + tid;
    float acc[NOUT];
    #pragma unroll
    for (int o = 0; o < NOUT; o++) acc[o] = b2[m * NOUT + o];

    const float4* hp = (const float4*)(g_h + (size_t)row * DHID + m * NH);
    #pragma unroll 4
    for (int kb = 0; kb < NH / 4; kb++) {
        float4 hv = hp[kb];
        float hvv[4] = {hv.x, hv.y, hv.z, hv.w};
        #pragma unroll
        for (int c = 0; c < 4; c++) {
            int k = kb * 4 + c;
            float4 w0 = *(const float4*)&Ws[k][0];
            float4 w1 = *(const float4*)&Ws[k][4];
            float2 w2 = *(const float2*)&Ws[k][8];
            acc[0] += hvv[c] * w0.x; acc[1] += hvv[c] * w0.y;
            acc[2] += hvv[c] * w0.z; acc[3] += hvv[c] * w0.w;
            acc[4] += hvv[c] * w1.x; acc[5] += hvv[c] * w1.y;
            acc[6] += hvv[c] * w1.z; acc[7] += hvv[c] * w1.w;
            acc[8] += hvv[c] * w2.x; acc[9] += hvv[c] * w2.y;
        }
    }
    float* yp = y + (size_t)row * (NM * NOUT) + m * NOUT;
    #pragma unroll
    for (int o = 0; o < NOUT; o++) yp[o] = acc[o];
}

extern "C" void kernel_launch(void* const* d_in, const int* in_sizes, int n_in,
                              void* d_out, int out_size) {
    const float* x  = (const float*)d_in[0];
    const float* W1 = (const float*)d_in[1];
    const float* b1 = (const float*)d_in[2];
    const float* W2 = (const float*)d_in[3];
    const float* b2 = (const float*)d_in[4];
    float* y = (float*)d_out;

    dim3 g1(NH / 128, BATCH / 128, NM);     // 4 x 64 x 8 = 2048 blocks
    mod_gemm1<<<g1, 256>>>(x, W1, b1);

    dim3 g2(BATCH / 256, NM);               // 32 x 8 = 256 blocks
    mod_gemm2<<<g2, 256>>>(W2, b2, y);
}

// round 3
// speedup vs baseline: 1.9069x; 1.9069x over previous
#include <cuda_runtime.h>
#include <cstdint>

typedef unsigned long long ull;

#define DIN   4096
#define NM    8
#define NH    512
#define NOUT  10

// ---- dynamic smem layout (bytes) ----
#define OFF_STAGE    0u          // 2 buffers x 4 tiles x (128 rows * 80B)
#define STAGE_STRIDE 40960u
#define T_AHI        0u
#define T_ALO        10240u
#define T_BHI        20480u
#define T_BLO        30720u
#define OFF_HBUF     81920u      // 128 * 134 * 4 = 68608
#define OFF_W2       150528u     // 512 * 12 * 4  = 24576
#define OFF_B1       175104u     // 512 * 4       = 2048
#define OFF_RED      177152u     // 128 * 6 * 8   = 6144
#define SMEM_TOTAL   183296u

static __device__ __forceinline__ uint32_t smem_u32(const void* p) {
    uint32_t a;
    asm("{ .reg .u64 t; cvta.to.shared.u64 t, %1; cvt.u32.u64 %0, t; }"
        : "=r"(a) : "l"(p));
    return a;
}
static __device__ __forceinline__ void ldsm4(uint32_t* r, uint32_t addr) {
    asm volatile("ldmatrix.sync.aligned.m8n8.x4.shared.b16 {%0,%1,%2,%3}, [%4];"
                 : "=r"(r[0]), "=r"(r[1]), "=r"(r[2]), "=r"(r[3]) : "r"(addr));
}
static __device__ __forceinline__ void mma16816(float* d, const uint32_t* a,
                                                uint32_t b0, uint32_t b1) {
    asm volatile("mma.sync.aligned.m16n8k16.row.col.f32.bf16.bf16.f32 "
                 "{%0,%1,%2,%3}, {%4,%5,%6,%7}, {%8,%9}, {%0,%1,%2,%3};"
                 : "+f"(d[0]), "+f"(d[1]), "+f"(d[2]), "+f"(d[3])
                 : "r"(a[0]), "r"(a[1]), "r"(a[2]), "r"(a[3]), "r"(b0), "r"(b1));
}
static __device__ __forceinline__ ull packdup(float v) {
    ull r;
    asm("mov.b64 %0, {%1, %1};" : "=l"(r) : "r"(__float_as_uint(v)));
    return r;
}
static __device__ __forceinline__ void fma2(ull& d, ull a, ull b) {
    asm("fma.rn.f32x2 %0, %1, %2, %0;" : "+l"(d) : "l"(a), "l"(b));
}
// convert float4 -> bf16 hi/lo pairs and store (4 halfs each) to smem
static __device__ __forceinline__ void cvt_sts(uint32_t hi_addr, uint32_t lo_addr,
                                               float4 v) {
    uint32_t h01, h23, l01, l23;
    asm("cvt.rn.bf16x2.f32 %0, %1, %2;" : "=r"(h01) : "f"(v.y), "f"(v.x));
    asm("cvt.rn.bf16x2.f32 %0, %1, %2;" : "=r"(h23) : "f"(v.w), "f"(v.z));
    float f0 = __uint_as_float(h01 << 16);
    float f1 = __uint_as_float(h01 & 0xffff0000u);
    float f2 = __uint_as_float(h23 << 16);
    float f3 = __uint_as_float(h23 & 0xffff0000u);
    asm("cvt.rn.bf16x2.f32 %0, %1, %2;" : "=r"(l01) : "f"(v.y - f1), "f"(v.x - f0));
    asm("cvt.rn.bf16x2.f32 %0, %1, %2;" : "=r"(l23) : "f"(v.w - f3), "f"(v.z - f2));
    asm volatile("st.shared.v2.b32 [%0], {%1,%2};" :: "r"(hi_addr), "r"(h01), "r"(h23) : "memory");
    asm volatile("st.shared.v2.b32 [%0], {%1,%2};" :: "r"(lo_addr), "r"(l01), "r"(l23) : "memory");
}

__global__ __launch_bounds__(256, 1)
void fused_mma(const float* __restrict__ x,  const float* __restrict__ W1,
               const float* __restrict__ b1, const float* __restrict__ W2,
               const float* __restrict__ b2, float* __restrict__ y) {
    extern __shared__ char smem[];
    const uint32_t sb = smem_u32(smem);
    const int tid  = threadIdx.x;
    const int wid  = tid >> 5;
    const int lane = tid & 31;
    const int m       = blockIdx.y;
    const int rowBase = blockIdx.x * 128;

    float* w2s  = (float*)(smem + OFF_W2);
    float* b1s  = (float*)(smem + OFF_B1);
    float* hbuf = (float*)(smem + OFF_HBUF);

    for (int i = tid; i < NH; i += 256) b1s[i] = b1[m * NH + i];
    #pragma unroll
    for (int o = 0; o < 12; o++)
        for (int c = tid; c < NH; c += 256)
            w2s[c * 12 + o] = (o < NOUT)
                ? W2[(size_t)(m * NOUT + o) * DIN + m * NH + c] : 0.f;

    const int wm = wid & 1;          // 2 m-tiles of 64
    const int wn = wid >> 1;         // 4 n-tiles of 32
    const uint32_t lmoff = (uint32_t)(lane & 15) * 80u + (uint32_t)(lane >> 4) * 16u;

    const float* xb = x + (size_t)rowBase * DIN + m * NH;

    ull acc2[5] = {0, 0, 0, 0, 0};   // layer-2 partials (10 outputs as f32x2)
    float4 av[4], bv[4];

    for (int p = 0; p < 4; p++) {
        const float* wb = W1 + (size_t)(m * NH + p * 128) * DIN + m * NH;

        float acc[4][4][4];
        #pragma unroll
        for (int i = 0; i < 4; i++)
            #pragma unroll
            for (int j = 0; j < 4; j++)
                #pragma unroll
                for (int q = 0; q < 4; q++) acc[i][j][q] = 0.f;

        // ---- prologue: load+convert chunk 0 ----
        #pragma unroll
        for (int s = 0; s < 4; s++) {
            int f = tid + s * 256, row = f >> 3, kq = f & 7;
            av[s] = *(const float4*)(xb + (size_t)row * DIN + kq * 4);
            bv[s] = *(const float4*)(wb + (size_t)row * DIN + kq * 4);
        }
        {
            uint32_t base = sb + OFF_STAGE;
            #pragma unroll
            for (int s = 0; s < 4; s++) {
                int f = tid + s * 256, row = f >> 3, kq = f & 7;
                uint32_t off = (uint32_t)row * 80u + (uint32_t)kq * 8u;
                cvt_sts(base + T_AHI + off, base + T_ALO + off, av[s]);
                cvt_sts(base + T_BHI + off, base + T_BLO + off, bv[s]);
            }
        }

        for (int c = 0; c < 16; c++) {
            __syncthreads();
            if (c < 15) {
                const int k0 = (c + 1) * 32;
                #pragma unroll
                for (int s = 0; s < 4; s++) {
                    int f = tid + s * 256, row = f >> 3, kq = f & 7;
                    av[s] = *(const float4*)(xb + (size_t)row * DIN + k0 + kq * 4);
                    bv[s] = *(const float4*)(wb + (size_t)row * DIN + k0 + kq * 4);
                }
            }
            // ---- MMA on buffer c&1 ----
            const uint32_t base = sb + OFF_STAGE + (uint32_t)(c & 1) * STAGE_STRIDE;
            #pragma unroll
            for (int ks = 0; ks < 2; ks++) {
                uint32_t ah[4][4], al[4][4], bhf[4][2], blf[4][2];
                #pragma unroll
                for (int i = 0; i < 4; i++) {
                    uint32_t off = (uint32_t)(wm * 64 + i * 16) * 80u + ks * 32u + lmoff;
                    ldsm4(ah[i], base + T_AHI + off);
                    ldsm4(al[i], base + T_ALO + off);
                }
                #pragma unroll
                for (int jj = 0; jj < 2; jj++) {
                    uint32_t off = (uint32_t)(wn * 32 + jj * 16) * 80u + ks * 32u + lmoff;
                    uint32_t rh[4], rl[4];
                    ldsm4(rh, base + T_BHI + off);
                    ldsm4(rl, base + T_BLO + off);
                    bhf[2 * jj][0] = rh[0]; bhf[2 * jj][1] = rh[2];
                    bhf[2 * jj + 1][0] = rh[1]; bhf[2 * jj + 1][1] = rh[3];
                    blf[2 * jj][0] = rl[0]; blf[2 * jj][1] = rl[2];
                    blf[2 * jj + 1][0] = rl[1]; blf[2 * jj + 1][1] = rl[3];
                }
                #pragma unroll
                for (int i = 0; i < 4; i++)
                    #pragma unroll
                    for (int j = 0; j < 4; j++) {
                        mma16816(acc[i][j], ah[i], bhf[j][0], bhf[j][1]);
                        mma16816(acc[i][j], ah[i], blf[j][0], blf[j][1]);
                        mma16816(acc[i][j], al[i], bhf[j][0], bhf[j][1]);
                    }
            }
            if (c < 15) {
                uint32_t nb = sb + OFF_STAGE + (uint32_t)((c + 1) & 1) * STAGE_STRIDE;
                #pragma unroll
                for (int s = 0; s < 4; s++) {
                    int f = tid + s * 256, row = f >> 3, kq = f & 7;
                    uint32_t off = (uint32_t)row * 80u + (uint32_t)kq * 8u;
                    cvt_sts(nb + T_AHI + off, nb + T_ALO + off, av[s]);
                    cvt_sts(nb + T_BHI + off, nb + T_BLO + off, bv[s]);
                }
            }
        }

        // ---- epilogue: bias + relu -> hbuf ----
        #pragma unroll
        for (int i = 0; i < 4; i++) {
            int r0 = wm * 64 + i * 16 + (lane >> 2);
            #pragma unroll
            for (int j = 0; j < 4; j++) {
                int c0 = wn * 32 + j * 8 + 2 * (lane & 3);
                float bb0 = b1s[p * 128 + c0], bb1 = b1s[p * 128 + c0 + 1];
                float2 v0, v1;
                v0.x = fmaxf(acc[i][j][0] + bb0, 0.f);
                v0.y = fmaxf(acc[i][j][1] + bb1, 0.f);
                v1.x = fmaxf(acc[i][j][2] + bb0, 0.f);
                v1.y = fmaxf(acc[i][j][3] + bb1, 0.f);
                *(float2*)(hbuf + (size_t)r0 * 134 + c0) = v0;
                *(float2*)(hbuf + (size_t)(r0 + 8) * 134 + c0) = v1;
            }
        }
        __syncthreads();

        // ---- fused layer 2 over this pass's 128 columns ----
        {
            const int r  = tid >> 1;
            const int hh = tid & 1;
            const float* hrow = hbuf + (size_t)r * 134;
            #pragma unroll 4
            for (int cc = 0; cc < 64; cc++) {
                int lc = 2 * cc + hh;
                float h = hrow[lc];
                ull hp = packdup(h);
                const ull* wp = (const ull*)(w2s + (size_t)(p * 128 + lc) * 12);
                fma2(acc2[0], hp, wp[0]);
                fma2(acc2[1], hp, wp[1]);
                fma2(acc2[2], hp, wp[2]);
                fma2(acc2[3], hp, wp[3]);
                fma2(acc2[4], hp, wp[4]);
            }
        }
        // next pass's first __syncthreads() orders hbuf reuse
    }

    // ---- combine the two threads per row, add b2, write y ----
    ull* red = (ull*)(smem + OFF_RED);
    const int r  = tid >> 1;
    const int hh = tid & 1;
    __syncthreads();
    if (hh == 1) {
        #pragma unroll
        for (int q = 0; q < 5; q++) red[r * 6 + q] = acc2[q];
    }
    __syncthreads();
    if (hh == 0) {
        float* yp = y + (size_t)(rowBase + r) * (NM * NOUT) + m * NOUT;
        #pragma unroll
        for (int q = 0; q < 5; q++) {
            ull o = red[r * 6 + q];
            float2 v;
            v.x = __uint_as_float((uint32_t)(acc2[q] & 0xffffffffu))
                + __uint_as_float((uint32_t)(o & 0xffffffffu))
                + b2[m * NOUT + 2 * q];
            v.y = __uint_as_float((uint32_t)(acc2[q] >> 32))
                + __uint_as_float((uint32_t)(o >> 32))
                + b2[m * NOUT + 2 * q + 1];
            ((float2*)yp)[q] = v;
        }
    }
}

extern "C" void kernel_launch(void* const* d_in, const int* in_sizes, int n_in,
                              void* d_out, int out_size) {
    const float* x  = (const float*)d_in[0];
    const float* W1 = (const float*)d_in[1];
    const float* b1 = (const float*)d_in[2];
    const float* W2 = (const float*)d_in[3];
    const float* b2 = (const float*)d_in[4];
    float* y = (float*)d_out;

    cudaFuncSetAttribute(fused_mma,
                         cudaFuncAttributeMaxDynamicSharedMemorySize, SMEM_TOTAL);
    dim3 grid(8192 / 128, NM);   // 512 CTAs
    fused_mma<<<grid, 256, SMEM_TOTAL>>>(x, W1, b1, W2, b2, y);
}

// round 4
// speedup vs baseline: 1.9572x; 1.0263x over previous
#include <cuda_runtime.h>
#include <cstdint>

typedef unsigned long long ull;

#define DIN   4096
#define NM    8
#define NH    512
#define NOUT  10

// ---- bf16 hi/lo pre-converted W1 diagonal blocks: [m][512 rows][512 k] ----
__device__ unsigned short g_w1hi[8u * 512u * 512u];
__device__ unsigned short g_w1lo[8u * 512u * 512u];

// ---- dynamic smem layout (bytes) ----
#define STAGE_STRIDE 40960u
#define T_AHI        0u
#define T_ALO        10240u
#define T_BHI        20480u
#define T_BLO        30720u
#define OFF_HBUF     81920u      // 128 * 132 * 4 = 67584
#define OFF_W2       149504u     // 512 * 12 * 4  = 24576
#define OFF_B1       174080u     // 512 * 4       = 2048
#define SMEM_TOTAL   176128u

static __device__ __forceinline__ uint32_t smem_u32(const void* p) {
    uint32_t a;
    asm("{ .reg .u64 t; cvta.to.shared.u64 t, %1; cvt.u32.u64 %0, t; }"
        : "=r"(a) : "l"(p));
    return a;
}
static __device__ __forceinline__ void ldsm4(uint32_t* r, uint32_t addr) {
    asm volatile("ldmatrix.sync.aligned.m8n8.x4.shared.b16 {%0,%1,%2,%3}, [%4];"
                 : "=r"(r[0]), "=r"(r[1]), "=r"(r[2]), "=r"(r[3]) : "r"(addr));
}
static __device__ __forceinline__ void mma16816(float* d, const uint32_t* a,
                                                uint32_t b0, uint32_t b1) {
    asm volatile("mma.sync.aligned.m16n8k16.row.col.f32.bf16.bf16.f32 "
                 "{%0,%1,%2,%3}, {%4,%5,%6,%7}, {%8,%9}, {%0,%1,%2,%3};"
                 : "+f"(d[0]), "+f"(d[1]), "+f"(d[2]), "+f"(d[3])
                 : "r"(a[0]), "r"(a[1]), "r"(a[2]), "r"(a[3]), "r"(b0), "r"(b1));
}
static __device__ __forceinline__ void cp16(uint32_t dst, const void* src) {
    asm volatile("cp.async.cg.shared.global [%0], [%1], 16;"
                 :: "r"(dst), "l"(src) : "memory");
}
static __device__ __forceinline__ void cp_commit() {
    asm volatile("cp.async.commit_group;" ::: "memory");
}
static __device__ __forceinline__ void cp_wait0() {
    asm volatile("cp.async.wait_group 0;" ::: "memory");
}
static __device__ __forceinline__ ull packdup(float v) {
    ull r;
    asm("mov.b64 %0, {%1, %1};" : "=l"(r) : "r"(__float_as_uint(v)));
    return r;
}
static __device__ __forceinline__ void fma2(ull& d, ull a, ull b) {
    asm("fma.rn.f32x2 %0, %1, %2, %0;" : "+l"(d) : "l"(a), "l"(b));
}
static __device__ __forceinline__ ull add2(ull a, ull b) {
    ull r;
    asm("add.rn.f32x2 %0, %1, %2;" : "=l"(r) : "l"(a), "l"(b));
    return r;
}
// split float4 into bf16 hi/lo packed pairs
static __device__ __forceinline__ void split4(float4 v, uint32_t& h01, uint32_t& h23,
                                              uint32_t& l01, uint32_t& l23) {
    asm("cvt.rn.bf16x2.f32 %0, %1, %2;" : "=r"(h01) : "f"(v.y), "f"(v.x));
    asm("cvt.rn.bf16x2.f32 %0, %1, %2;" : "=r"(h23) : "f"(v.w), "f"(v.z));
    float f0 = __uint_as_float(h01 << 16);
    float f1 = __uint_as_float(h01 & 0xffff0000u);
    float f2 = __uint_as_float(h23 << 16);
    float f3 = __uint_as_float(h23 & 0xffff0000u);
    asm("cvt.rn.bf16x2.f32 %0, %1, %2;" : "=r"(l01) : "f"(v.y - f1), "f"(v.x - f0));
    asm("cvt.rn.bf16x2.f32 %0, %1, %2;" : "=r"(l23) : "f"(v.w - f3), "f"(v.z - f2));
}
static __device__ __forceinline__ void sts8(uint32_t addr, uint32_t a, uint32_t b) {
    asm volatile("st.shared.v2.b32 [%0], {%1,%2};" :: "r"(addr), "r"(a), "r"(b) : "memory");
}

// ---------------- pre-pass: W1 diag blocks -> bf16 hi/lo ----------------
__global__ __launch_bounds__(256)
void cvt_w1(const float* __restrict__ W1) {
    int g = blockIdx.x * 256 + threadIdx.x;       // 0..524287 float4s
    int m = g >> 16;
    int rem = g & 65535;
    int r = rem >> 7;
    int c4 = rem & 127;
    float4 v = *(const float4*)(W1 + (size_t)(m * 512 + r) * DIN + m * 512 + c4 * 4);
    uint32_t h01, h23, l01, l23;
    split4(v, h01, h23, l01, l23);
    size_t off = ((size_t)(m * 512 + r) * 512 + c4 * 4);
    *(uint2*)(g_w1hi + off) = make_uint2(h01, h23);
    *(uint2*)(g_w1lo + off) = make_uint2(l01, l23);
}

// ---------------- main fused kernel: 512 threads, 16 warps ----------------
__global__ __launch_bounds__(512, 1)
void fused_mma(const float* __restrict__ x,  const float* __restrict__ b1,
               const float* __restrict__ W2, const float* __restrict__ b2,
               float* __restrict__ y) {
    extern __shared__ char smem[];
    const uint32_t sb = smem_u32(smem);
    const int tid  = threadIdx.x;
    const int wid  = tid >> 5;
    const int lane = tid & 31;
    const int m       = blockIdx.y;
    const int rowBase = blockIdx.x * 128;

    float* w2s  = (float*)(smem + OFF_W2);
    float* b1s  = (float*)(smem + OFF_B1);
    float* hbuf = (float*)(smem + OFF_HBUF);

    for (int i = tid; i < NH; i += 512) b1s[i] = b1[m * NH + i];
    for (int idx = tid; idx < NH * 12; idx += 512) {
        int c = idx / 12, o = idx - c * 12;
        w2s[idx] = (o < NOUT) ? W2[(size_t)(m * NOUT + o) * DIN + m * NH + c] : 0.f;
    }

    const int wm = wid & 3;           // 4 m-tiles of 32
    const int wn = wid >> 2;          // 4 n-tiles of 32
    const uint32_t lmoff = (uint32_t)(lane & 15) * 80u + (uint32_t)(lane >> 4) * 16u;

    const float* xb = x + (size_t)rowBase * DIN + m * NH;
    const int rowA[2] = { tid >> 3, (tid + 512) >> 3 };
    const int kqA[2]  = { tid & 7, tid & 7 };

    // stage B (hi+lo) for (pass p2, k0) into buf via cp.async
    auto stageB = [&](int p2, int k0, uint32_t buf) {
        #pragma unroll
        for (int s = 0; s < 2; s++) {
            int f  = tid + s * 512;
            int hl = f >> 9;
            int fr = f & 511;
            int br = fr >> 2, c4 = fr & 3;
            const unsigned short* src = (hl ? g_w1lo : g_w1hi)
                + ((size_t)(m * 512 + p2 * 128 + br) * 512 + k0 + c4 * 8);
            cp16(buf + (hl ? T_BLO : T_BHI) + (uint32_t)br * 80u + (uint32_t)c4 * 16u, src);
        }
        cp_commit();
    };

    ull acc2[5] = {0, 0, 0, 0, 0};
    float4 av[2];

    // prologue: chunk (p=0, c=0) into buffer 0
    {
        #pragma unroll
        for (int s = 0; s < 2; s++)
            av[s] = *(const float4*)(xb + (size_t)rowA[s] * DIN + kqA[s] * 4);
        stageB(0, 0, sb);
        #pragma unroll
        for (int s = 0; s < 2; s++) {
            uint32_t h01, h23, l01, l23;
            split4(av[s], h01, h23, l01, l23);
            uint32_t off = (uint32_t)rowA[s] * 80u + (uint32_t)kqA[s] * 8u;
            sts8(sb + T_AHI + off, h01, h23);
            sts8(sb + T_ALO + off, l01, l23);
        }
    }

    for (int p = 0; p < 4; p++) {
        float acc[2][4][4];
        #pragma unroll
        for (int i = 0; i < 2; i++)
            #pragma unroll
            for (int j = 0; j < 4; j++)
                #pragma unroll
                for (int q = 0; q < 4; q++) acc[i][j][q] = 0.f;

        for (int c = 0; c < 16; c++) {
            cp_wait0();
            __syncthreads();

            const bool pre = !(p == 3 && c == 15);
            const int np = (c == 15) ? p + 1 : p;
            const int nk = (c == 15) ? 0 : (c + 1) * 32;
            const uint32_t nbuf = sb + (uint32_t)((c + 1) & 1) * STAGE_STRIDE;
            if (pre) {
                #pragma unroll
                for (int s = 0; s < 2; s++)
                    av[s] = *(const float4*)(xb + (size_t)rowA[s] * DIN + nk + kqA[s] * 4);
                stageB(np, nk, nbuf);
            }

            const uint32_t base = sb + (uint32_t)(c & 1) * STAGE_STRIDE;
            #pragma unroll
            for (int ks = 0; ks < 2; ks++) {
                uint32_t ah[2][4], al[2][4], bhf[4][2], blf[4][2];
                #pragma unroll
                for (int i = 0; i < 2; i++) {
                    uint32_t off = (uint32_t)(wm * 32 + i * 16) * 80u + ks * 32u + lmoff;
                    ldsm4(ah[i], base + T_AHI + off);
                    ldsm4(al[i], base + T_ALO + off);
                }
                #pragma unroll
                for (int jj = 0; jj < 2; jj++) {
                    uint32_t off = (uint32_t)(wn * 32 + jj * 16) * 80u + ks * 32u + lmoff;
                    uint32_t rh[4], rl[4];
                    ldsm4(rh, base + T_BHI + off);
                    ldsm4(rl, base + T_BLO + off);
                    bhf[2 * jj][0] = rh[0]; bhf[2 * jj][1] = rh[2];
                    bhf[2 * jj + 1][0] = rh[1]; bhf[2 * jj + 1][1] = rh[3];
                    blf[2 * jj][0] = rl[0]; blf[2 * jj][1] = rl[2];
                    blf[2 * jj + 1][0] = rl[1]; blf[2 * jj + 1][1] = rl[3];
                }
                #pragma unroll
                for (int i = 0; i < 2; i++)
                    #pragma unroll
                    for (int j = 0; j < 4; j++) {
                        mma16816(acc[i][j], ah[i], bhf[j][0], bhf[j][1]);
                        mma16816(acc[i][j], ah[i], blf[j][0], blf[j][1]);
                        mma16816(acc[i][j], al[i], bhf[j][0], bhf[j][1]);
                    }
            }

            if (pre) {
                #pragma unroll
                for (int s = 0; s < 2; s++) {
                    uint32_t h01, h23, l01, l23;
                    split4(av[s], h01, h23, l01, l23);
                    uint32_t off = (uint32_t)rowA[s] * 80u + (uint32_t)kqA[s] * 8u;
                    sts8(nbuf + T_AHI + off, h01, h23);
                    sts8(nbuf + T_ALO + off, l01, l23);
                }
            }
        }

        // ---- epilogue: bias + relu -> hbuf (pitch 132) ----
        #pragma unroll
        for (int i = 0; i < 2; i++) {
            int r0 = wm * 32 + i * 16 + (lane >> 2);
            #pragma unroll
            for (int j = 0; j < 4; j++) {
                int c0 = wn * 32 + j * 8 + 2 * (lane & 3);
                float bb0 = b1s[p * 128 + c0], bb1 = b1s[p * 128 + c0 + 1];
                float2 v0, v1;
                v0.x = fmaxf(acc[i][j][0] + bb0, 0.f);
                v0.y = fmaxf(acc[i][j][1] + bb1, 0.f);
                v1.x = fmaxf(acc[i][j][2] + bb0, 0.f);
                v1.y = fmaxf(acc[i][j][3] + bb1, 0.f);
                *(float2*)(hbuf + (size_t)r0 * 132 + c0) = v0;
                *(float2*)(hbuf + (size_t)(r0 + 8) * 132 + c0) = v1;
            }
        }
        __syncthreads();

        // ---- fused layer 2: 4 threads per row, interleaved cols (bank-safe) ----
        {
            const int lr = tid >> 2;
            const int q  = tid & 3;
            const float* hrow = hbuf + (size_t)lr * 132;
            #pragma unroll 8
            for (int cc = 0; cc < 32; cc++) {
                int lc = q + 4 * cc;
                ull hp = packdup(hrow[lc]);
                const ull* wp = (const ull*)(w2s + (size_t)(p * 128 + lc) * 12);
                fma2(acc2[0], hp, wp[0]);
                fma2(acc2[1], hp, wp[1]);
                fma2(acc2[2], hp, wp[2]);
                fma2(acc2[3], hp, wp[3]);
                fma2(acc2[4], hp, wp[4]);
            }
        }
    }

    // ---- reduce the 4 threads per row (quad shuffles), add b2, store ----
    #pragma unroll
    for (int q5 = 0; q5 < 5; q5++) {
        acc2[q5] = add2(acc2[q5], __shfl_down_sync(0xffffffffu, acc2[q5], 1, 4));
        acc2[q5] = add2(acc2[q5], __shfl_down_sync(0xffffffffu, acc2[q5], 2, 4));
    }
    if ((tid & 3) == 0) {
        const int lr = tid >> 2;
        float* yp = y + (size_t)(rowBase + lr) * (NM * NOUT) + m * NOUT;
        #pragma unroll
        for (int q5 = 0; q5 < 5; q5++) {
            float2 v;
            v.x = __uint_as_float((uint32_t)(acc2[q5] & 0xffffffffu)) + b2[m * NOUT + 2 * q5];
            v.y = __uint_as_float((uint32_t)(acc2[q5] >> 32)) + b2[m * NOUT + 2 * q5 + 1];
            ((float2*)yp)[q5] = v;
        }
    }
}

extern "C" void kernel_launch(void* const* d_in, const int* in_sizes, int n_in,
                              void* d_out, int out_size) {
    const float* x  = (const float*)d_in[0];
    const float* W1 = (const float*)d_in[1];
    const float* b1 = (const float*)d_in[2];
    const float* W2 = (const float*)d_in[3];
    const float* b2 = (const float*)d_in[4];
    float* y = (float*)d_out;

    cvt_w1<<<2048, 256>>>(W1);

    cudaFuncSetAttribute(fused_mma,
                         cudaFuncAttributeMaxDynamicSharedMemorySize, SMEM_TOTAL);
    dim3 grid(8192 / 128, NM);   // 512 CTAs
    fused_mma<<<grid, 512, SMEM_TOTAL>>>(x, b1, W2, b2, y);
}